// round 15
// baseline (speedup 1.0000x reference)
#include <cuda_runtime.h>
#include <cuda_fp16.h>
#include <cstdint>

#define EMB   768
#define EMB3  2304
#define NHEAD 12
#define HDIM  64
#define SEQ   1024
#define BATCH 8
#define MROWS (BATCH * SEQ)   // 8192

// Q pre-scale: 0.125 * log2(e)  (folded into Q at GEMM1 epilogue)
#define QSCALE 0.1803368787f

// ---------------------------------------------------------------------------
// Scratch (no cudaMalloc allowed).
// ---------------------------------------------------------------------------
__device__ __align__(256) __half g_x16 [(size_t)MROWS * EMB];       // x fp16
__device__ __align__(256) __half g_wat16[(size_t)EMB3 * EMB];       // W_attn^T [N,K] fp16
__device__ __align__(256) __half g_wpt16[(size_t)EMB * EMB];        // W_proj^T [N,K] fp16
__device__ __align__(256) __half g_qk16[(size_t)MROWS * 2 * EMB];   // Qs|K fp16 [M,1536]
__device__ __align__(256) __half g_vt16[(size_t)BATCH * NHEAD * HDIM * SEQ]; // V^T fp16 [B,H,d,t]
__device__ __align__(256) __half g_at16[(size_t)MROWS * EMB];       // attn out fp16

// ---------------------------------------------------------------------------
// Helpers
// ---------------------------------------------------------------------------
__device__ __forceinline__ void cpa16(void* smem_dst, const void* gmem_src) {
    uint32_t s = (uint32_t)__cvta_generic_to_shared(smem_dst);
    asm volatile("cp.async.cg.shared.global [%0], [%1], 16;\n" :: "r"(s), "l"(gmem_src));
}
__device__ __forceinline__ void cpa_commit() { asm volatile("cp.async.commit_group;\n"); }
template<int N>
__device__ __forceinline__ void cpa_wait() { asm volatile("cp.async.wait_group %0;\n" :: "n"(N) : "memory"); }

__device__ __forceinline__ void mma_f16(float& d0, float& d1, float& d2, float& d3,
                                        uint32_t a0, uint32_t a1, uint32_t a2, uint32_t a3,
                                        uint32_t b0, uint32_t b1) {
    asm volatile(
        "mma.sync.aligned.m16n8k16.row.col.f32.f16.f16.f32 "
        "{%0,%1,%2,%3}, {%4,%5,%6,%7}, {%8,%9}, {%0,%1,%2,%3};\n"
        : "+f"(d0), "+f"(d1), "+f"(d2), "+f"(d3)
        : "r"(a0), "r"(a1), "r"(a2), "r"(a3), "r"(b0), "r"(b1));
}

__device__ __forceinline__ void ldsm4(uint32_t& r0, uint32_t& r1,
                                      uint32_t& r2, uint32_t& r3, uint32_t addr) {
    asm volatile("ldmatrix.sync.aligned.m8n8.x4.shared.b16 {%0,%1,%2,%3}, [%4];"
                 : "=r"(r0), "=r"(r1), "=r"(r2), "=r"(r3) : "r"(addr));
}

__device__ __forceinline__ uint32_t pack_f16x2(float lo, float hi) {
    uint32_t u;
    asm("cvt.rn.f16x2.f32 %0, %1, %2;" : "=r"(u) : "f"(hi), "f"(lo));
    return u;
}

__device__ __forceinline__ float ex2f(float x) {
    float y;
    asm("ex2.approx.f32 %0, %1;" : "=f"(y) : "f"(x));
    return y;
}

// Two-lane fp16 exp2 (one MUFU op for two values)
__device__ __forceinline__ uint32_t h2ex2(uint32_t x) {
    uint32_t y;
    asm("ex2.approx.f16x2 %0, %1;" : "=r"(y) : "r"(x));
    return y;
}

// ---------------------------------------------------------------------------
// Pre-pass 1: fp32 -> fp16 (float4 -> 2x half2)
// ---------------------------------------------------------------------------
__global__ void cvt_fp16_kernel(const float* __restrict__ in, __half* __restrict__ out, int n4)
{
    int i = blockIdx.x * blockDim.x + threadIdx.x;
    if (i < n4) {
        float4 v = ((const float4*)in)[i];
        ((__half2*)out)[2 * i]     = __floats2half2_rn(v.x, v.y);
        ((__half2*)out)[2 * i + 1] = __floats2half2_rn(v.z, v.w);
    }
}

// ---------------------------------------------------------------------------
// Pre-pass 2: W[K,N] fp32 -> W^T[N,K] fp16 (32x32 smem-tiled transpose)
// ---------------------------------------------------------------------------
__global__ void transpose_fp16_kernel(const float* __restrict__ W,
                                      __half* __restrict__ T, int K, int N)
{
    __shared__ float t[32][33];
    const int tx = threadIdx.x, ty = threadIdx.y;
    const int n0 = blockIdx.x * 32, k0 = blockIdx.y * 32;
#pragma unroll
    for (int i = 0; i < 4; i++)
        t[ty + i * 8][tx] = W[(size_t)(k0 + ty + i * 8) * N + n0 + tx];
    __syncthreads();
#pragma unroll
    for (int i = 0; i < 4; i++) {
        const int n = ty + i * 8;
        T[(size_t)(n0 + n) * K + k0 + tx] = __float2half_rn(t[tx][n]);
    }
}

// ---------------------------------------------------------------------------
// FP16 tensor-core GEMM: C = A @ B^T + bias.
// A=[M,K] fp16, B=[N,K] fp16.  MT x 128 tile, BK=96 (8 barriers for K=768),
// 256 thr = 8 warps (2m x 4n), m16n8k16, ldmatrix, pitch 52 words
// (13 16B-chunks/row; 13 = 5 mod 8, gcd(5,8)=1 -> conflict-free ldmatrix).
// MODE 0: C fp32 [M,N]; MODE 1 (MT=128): QKV layout, Q pre-scaled by QSCALE.
// ---------------------------------------------------------------------------
#define GW 52   // smem pitch in 32-bit words (48 data + 4 pad)

template<int MODE, int MT>
__global__ __launch_bounds__(256)
void gemm_fp16_kernel(const __half* __restrict__ A, const __half* __restrict__ B,
                      const float* __restrict__ bias, float* __restrict__ C,
                      __half* __restrict__ QK, __half* __restrict__ VT,
                      int M, int N, int K)
{
    constexpr int MI = MT / 32;            // m16 tiles per warp_m slab
    constexpr int AW = MT * GW;            // A part words per stage
    constexpr int SW = AW + 128 * GW;      // stage words

    extern __shared__ uint32_t gsm[];

    const int tid    = threadIdx.x;
    const int lane   = tid & 31;
    const int warp   = tid >> 5;
    const int warp_m = warp >> 2;
    const int warp_n = warp & 3;
    const int gr     = lane >> 2;
    const int gc     = lane & 3;

    const int brow = blockIdx.y * MT;
    const int bcol = blockIdx.x * 128;

    // ldmatrix per-lane offsets (in words)
    const int lrow8 = lane & 7;
    const int segA  = (lane >> 3) & 1;
    const int segAc = lane >> 4;
    const int aLw = (segA * 8 + lrow8) * GW + segAc * 4;
    const int bLw = (segAc * 8 + lrow8) * GW + segA * 4;

    const uint32_t smb = (uint32_t)__cvta_generic_to_shared(gsm);

    float acc[MI][4][4];
#pragma unroll
    for (int i = 0; i < MI; i++)
#pragma unroll
        for (int j = 0; j < 4; j++)
#pragma unroll
            for (int v = 0; v < 4; v++) acc[i][j][v] = 0.f;

    const int NCH = K / 96;

    // Stage loader: A = MT rows x 12 16B-units, B = 128 rows x 12 units
    auto load_stage = [&](int s, int kc) {
        uint32_t* st = gsm + s * SW;
#pragma unroll
        for (int i = tid; i < MT * 12; i += 256) {
            const int r = i / 12, u = i % 12;
            cpa16(st + r * GW + u * 4, A + (size_t)(brow + r) * K + kc + u * 8);
        }
#pragma unroll
        for (int i = tid; i < 128 * 12; i += 256) {
            const int r = i / 12, u = i % 12;
            cpa16(st + AW + r * GW + u * 4, B + (size_t)(bcol + r) * K + kc + u * 8);
        }
    };

    load_stage(0, 0);
    cpa_commit();

    int buf = 0;
    for (int c = 0; c < NCH; c++) {
        cpa_wait<0>();
        __syncthreads();

        if (c + 1 < NCH) {
            load_stage(buf ^ 1, (c + 1) * 96);
            cpa_commit();
        }

        const uint32_t aBase = smb + (uint32_t)(buf * SW) * 4;
        const uint32_t bBase = smb + (uint32_t)(buf * SW + AW) * 4;

#pragma unroll
        for (int ks = 0; ks < 6; ks++) {
            const int w0 = ks * 8;
            uint32_t af[MI][4], bf[4][2];
#pragma unroll
            for (int mi = 0; mi < MI; mi++)
                ldsm4(af[mi][0], af[mi][1], af[mi][2], af[mi][3],
                      aBase + (uint32_t)(((warp_m * (MT / 2) + mi * 16) * GW + w0 + aLw) * 4));
#pragma unroll
            for (int p = 0; p < 2; p++)
                ldsm4(bf[2 * p][0], bf[2 * p][1], bf[2 * p + 1][0], bf[2 * p + 1][1],
                      bBase + (uint32_t)(((warp_n * 32 + p * 16) * GW + w0 + bLw) * 4));
#pragma unroll
            for (int mi = 0; mi < MI; mi++)
#pragma unroll
                for (int ni = 0; ni < 4; ni++)
                    mma_f16(acc[mi][ni][0], acc[mi][ni][1],
                            acc[mi][ni][2], acc[mi][ni][3],
                            af[mi][0], af[mi][1], af[mi][2], af[mi][3],
                            bf[ni][0], bf[ni][1]);
        }
        buf ^= 1;
    }

    // Epilogue
#pragma unroll
    for (int ni = 0; ni < 4; ni++) {
        const int col = bcol + warp_n * 32 + ni * 8 + 2 * gc;
        const float bv0 = bias[col];
        const float bv1 = bias[col + 1];
#pragma unroll
        for (int mi = 0; mi < MI; mi++) {
            const int row = brow + warp_m * (MT / 2) + mi * 16 + gr;
            float v00 = acc[mi][ni][0] + bv0, v01 = acc[mi][ni][1] + bv1;
            float v10 = acc[mi][ni][2] + bv0, v11 = acc[mi][ni][3] + bv1;
            if (MODE == 0) {
                *(float2*)&C[(size_t)row * N + col]       = make_float2(v00, v01);
                *(float2*)&C[(size_t)(row + 8) * N + col] = make_float2(v10, v11);
            } else {
                if (col < 1536) {
                    if (col < 768) {   // Q: fold in softmax scale (log2 domain)
                        v00 *= QSCALE; v01 *= QSCALE; v10 *= QSCALE; v11 *= QSCALE;
                    }
                    *(__half2*)&QK[(size_t)row * 1536 + col] = __floats2half2_rn(v00, v01);
                    *(__half2*)&QK[(size_t)(row + 8) * 1536 + col] = __floats2half2_rn(v10, v11);
                } else {
                    const int cc = col - 1536;
                    const int h  = cc >> 6;
                    const int d0 = cc & 63;
                    const int b  = row >> 10;
                    const int t  = row & 1023;
                    __half* base = VT + ((size_t)(b * NHEAD + h) * HDIM) * SEQ;
                    base[(size_t)d0 * SEQ + t]           = __float2half_rn(v00);
                    base[(size_t)(d0 + 1) * SEQ + t]     = __float2half_rn(v01);
                    base[(size_t)d0 * SEQ + t + 8]       = __float2half_rn(v10);
                    base[(size_t)(d0 + 1) * SEQ + t + 8] = __float2half_rn(v11);
                }
            }
        }
    }
}

#define G1_SMEM (2 * (128 + 128) * GW * 4)   // 106496 B
#define G2_SMEM (2 * (64 + 128) * GW * 4)    // 79872 B

// ---------------------------------------------------------------------------
// FP16 tensor-core flash attention (causal, m16n8k16, log2-domain softmax,
// exp via ex2.approx.f16x2 fused with the P fp16 pack).
// ---------------------------------------------------------------------------
#define APW 36
#define AT2_SMEM ((128 * APW + 2 * 64 * APW + 2 * 64 * APW) * 4)

__global__ __launch_bounds__(256, 2)
void attn_f16_kernel(const __half* __restrict__ qk, const __half* __restrict__ vt,
                     __half* __restrict__ out16)
{
    extern __shared__ uint32_t smw[];
    uint32_t* QP  = smw;                   // 128 x APW : Q tile, later P strips
    uint32_t* Ks0 = QP + 128 * APW;        // 2 x 64 x APW
    uint32_t* Vt0 = Ks0 + 2 * 64 * APW;    // 2 x 64 x APW

    const int tid  = threadIdx.x;
    const int lane = tid & 31;
    const int warp = tid >> 5;
    const int gr   = lane >> 2;
    const int gc   = lane & 3;

    const int bh = blockIdx.y;
    const int b  = bh / NHEAD;
    const int h  = bh % NHEAD;
    const int qt = 7 - blockIdx.x;
    const int qbase = qt * 128;
    const int ktmax = 2 * qt + 1;

    const int lrow8 = lane & 7;
    const int segA  = (lane >> 3) & 1;
    const int segAc = lane >> 4;
    const int aLw = (segA * 8 + lrow8) * APW + segAc * 4;
    const int bLw = (segAc * 8 + lrow8) * APW + segA * 4;

    const uint32_t qpb = (uint32_t)__cvta_generic_to_shared(QP);
    const uint32_t ksb = (uint32_t)__cvta_generic_to_shared(Ks0);
    const uint32_t vtb = (uint32_t)__cvta_generic_to_shared(Vt0);

    // Q tile load
    {
        const int r = tid >> 1;
        const int u = (tid & 1) * 4;
        const __half* src = qk + (size_t)(b * SEQ + qbase + r) * 1536 + h * HDIM + u * 8;
        uint32_t* dst = QP + r * APW + u * 4;
#pragma unroll
        for (int i = 0; i < 4; i++)
            cpa16(dst + 4 * i, src + 8 * i);
    }
    // K + Vt tile 0
    {
        const int r = tid >> 2;
        const int u = (tid & 3) * 2;
        const __half* ksrc = qk + (size_t)(b * SEQ + r) * 1536 + 768 + h * HDIM + u * 8;
        const __half* vsrc = vt + ((size_t)(b * NHEAD + h) * HDIM + r) * SEQ + u * 8;
        cpa16(Ks0 + r * APW + u * 4,     ksrc);
        cpa16(Ks0 + r * APW + u * 4 + 4, ksrc + 8);
        cpa16(Vt0 + r * APW + u * 4,     vsrc);
        cpa16(Vt0 + r * APW + u * 4 + 4, vsrc + 8);
    }
    cpa_commit();
    cpa_wait<0>();
    __syncthreads();

    uint32_t qf[4][4];
#pragma unroll
    for (int c = 0; c < 4; c++)
        ldsm4(qf[c][0], qf[c][1], qf[c][2], qf[c][3],
              qpb + (uint32_t)(((warp * 16) * APW + c * 8 + aLw) * 4));

    float o[8][4];
#pragma unroll
    for (int i = 0; i < 8; i++)
#pragma unroll
        for (int j = 0; j < 4; j++) o[i][j] = 0.f;
    float mr0 = -1e30f, mr1 = -1e30f, l0 = 0.f, l1 = 0.f;

    const int lrow = warp * 16 + gr;
    const int grow0 = qbase + lrow;
    const int prow0 = lrow * APW;
    const int prow1 = (lrow + 8) * APW;

    int buf = 0;
    for (int kt = 0; kt <= ktmax; kt++) {
        const int kbase = kt * 64;
        cpa_wait<0>();
        __syncthreads();

        if (kt < ktmax) {
            const int r = tid >> 2;
            const int u = (tid & 3) * 2;
            const __half* ksrc = qk + (size_t)(b * SEQ + (kt + 1) * 64 + r) * 1536
                                 + 768 + h * HDIM + u * 8;
            const __half* vsrc = vt + ((size_t)(b * NHEAD + h) * HDIM + r) * SEQ
                                 + (kt + 1) * 64 + u * 8;
            uint32_t* kd = Ks0 + (buf ^ 1) * 64 * APW + r * APW + u * 4;
            uint32_t* vd = Vt0 + (buf ^ 1) * 64 * APW + r * APW + u * 4;
            cpa16(kd,     ksrc);
            cpa16(kd + 4, ksrc + 8);
            cpa16(vd,     vsrc);
            cpa16(vd + 4, vsrc + 8);
            cpa_commit();
        }

        if (kbase > qbase + warp * 16 + 15) { buf ^= 1; continue; }

        // ---- S' = Qs @ K^T  (log2 domain) ----
        float s[8][4];
#pragma unroll
        for (int i = 0; i < 8; i++)
#pragma unroll
            for (int j = 0; j < 4; j++) s[i][j] = 0.f;

        const uint32_t kBase = ksb + (uint32_t)buf * (64 * APW * 4);
#pragma unroll
        for (int c = 0; c < 4; c++) {
            const int w0 = c * 8;
            uint32_t bf[8][2];
#pragma unroll
            for (int p = 0; p < 4; p++)
                ldsm4(bf[2 * p][0], bf[2 * p][1], bf[2 * p + 1][0], bf[2 * p + 1][1],
                      kBase + (uint32_t)(((p * 16) * APW + w0 + bLw) * 4));
#pragma unroll
            for (int nt = 0; nt < 8; nt++)
                mma_f16(s[nt][0], s[nt][1], s[nt][2], s[nt][3],
                        qf[c][0], qf[c][1], qf[c][2], qf[c][3],
                        bf[nt][0], bf[nt][1]);
        }

        // ---- causal mask ----
        if (kbase + 63 > grow0) {
            const int lr0 = grow0;
            const int lr1 = grow0 + 8;
#pragma unroll
            for (int nt = 0; nt < 8; nt++) {
                const int c0 = kbase + nt * 8 + 2 * gc;
                if (c0     > lr0) s[nt][0] = -1e30f;
                if (c0 + 1 > lr0) s[nt][1] = -1e30f;
                if (c0     > lr1) s[nt][2] = -1e30f;
                if (c0 + 1 > lr1) s[nt][3] = -1e30f;
            }
        }

        // ---- online softmax (log2 domain; P = 2^(S-m) via f16x2 MUFU) ----
        float mx0 = -1e30f, mx1 = -1e30f;
#pragma unroll
        for (int nt = 0; nt < 8; nt++) {
            mx0 = fmaxf(mx0, fmaxf(s[nt][0], s[nt][1]));
            mx1 = fmaxf(mx1, fmaxf(s[nt][2], s[nt][3]));
        }
        mx0 = fmaxf(mx0, __shfl_xor_sync(0xffffffffu, mx0, 1));
        mx0 = fmaxf(mx0, __shfl_xor_sync(0xffffffffu, mx0, 2));
        mx1 = fmaxf(mx1, __shfl_xor_sync(0xffffffffu, mx1, 1));
        mx1 = fmaxf(mx1, __shfl_xor_sync(0xffffffffu, mx1, 2));

        const float mn0 = fmaxf(mr0, mx0);
        const float mn1 = fmaxf(mr1, mx1);
        const float a0  = ex2f(mr0 - mn0);
        const float a1  = ex2f(mr1 - mn1);
        mr0 = mn0; mr1 = mn1;

        // P = 2^(s-m): pack pair -> one f16x2 ex2 -> store; sum via fp32 unpack
        float sum0 = 0.f, sum1 = 0.f;
#pragma unroll
        for (int nt = 0; nt < 8; nt++) {
            uint32_t p01 = h2ex2(pack_f16x2(s[nt][0] - mn0, s[nt][1] - mn0));
            uint32_t p23 = h2ex2(pack_f16x2(s[nt][2] - mn1, s[nt][3] - mn1));
            QP[prow0 + nt * 4 + gc] = p01;
            QP[prow1 + nt * 4 + gc] = p23;
            float2 f0 = __half22float2(*reinterpret_cast<__half2*>(&p01));
            float2 f1 = __half22float2(*reinterpret_cast<__half2*>(&p23));
            sum0 += f0.x + f0.y;
            sum1 += f1.x + f1.y;
        }
        sum0 += __shfl_xor_sync(0xffffffffu, sum0, 1);
        sum0 += __shfl_xor_sync(0xffffffffu, sum0, 2);
        sum1 += __shfl_xor_sync(0xffffffffu, sum1, 1);
        sum1 += __shfl_xor_sync(0xffffffffu, sum1, 2);
        l0 = l0 * a0 + sum0;
        l1 = l1 * a1 + sum1;

#pragma unroll
        for (int nt = 0; nt < 8; nt++) {
            o[nt][0] *= a0; o[nt][1] *= a0;
            o[nt][2] *= a1; o[nt][3] *= a1;
        }
        __syncwarp();

        // ---- O += P @ V ----
        const uint32_t vBase = vtb + (uint32_t)buf * (64 * APW * 4);
#pragma unroll
        for (int c = 0; c < 4; c++) {
            const int w0 = c * 8;
            uint32_t af[4];
            ldsm4(af[0], af[1], af[2], af[3],
                  qpb + (uint32_t)(((warp * 16) * APW + w0 + aLw) * 4));
            uint32_t bf[8][2];
#pragma unroll
            for (int p = 0; p < 4; p++)
                ldsm4(bf[2 * p][0], bf[2 * p][1], bf[2 * p + 1][0], bf[2 * p + 1][1],
                      vBase + (uint32_t)(((p * 16) * APW + w0 + bLw) * 4));
#pragma unroll
            for (int nt = 0; nt < 8; nt++)
                mma_f16(o[nt][0], o[nt][1], o[nt][2], o[nt][3],
                        af[0], af[1], af[2], af[3],
                        bf[nt][0], bf[nt][1]);
        }
        __syncwarp();
        buf ^= 1;
    }

    // ---- epilogue ----
    const float inv0 = 1.f / l0;
    const float inv1 = 1.f / l1;
    const int r0g = b * SEQ + grow0;
#pragma unroll
    for (int nt = 0; nt < 8; nt++) {
        const int col = h * HDIM + nt * 8 + 2 * gc;
        *(__half2*)&out16[(size_t)r0g * EMB + col] =
            __floats2half2_rn(o[nt][0] * inv0, o[nt][1] * inv0);
        *(__half2*)&out16[(size_t)(r0g + 8) * EMB + col] =
            __floats2half2_rn(o[nt][2] * inv1, o[nt][3] * inv1);
    }
}

// ---------------------------------------------------------------------------
extern "C" void kernel_launch(void* const* d_in, const int* in_sizes, int n_in,
                              void* d_out, int out_size)
{
    const float* x      = (const float*)d_in[0];
    const float* W_attn = (const float*)d_in[1];
    const float* b_attn = (const float*)d_in[2];
    const float* W_proj = (const float*)d_in[3];
    const float* b_proj = (const float*)d_in[4];
    float* out = (float*)d_out;

    __half *x16, *wat16, *wpt16, *qk16, *vt16, *at16;
    cudaGetSymbolAddress((void**)&x16,   g_x16);
    cudaGetSymbolAddress((void**)&wat16, g_wat16);
    cudaGetSymbolAddress((void**)&wpt16, g_wpt16);
    cudaGetSymbolAddress((void**)&qk16,  g_qk16);
    cudaGetSymbolAddress((void**)&vt16,  g_vt16);
    cudaGetSymbolAddress((void**)&at16,  g_at16);

    cudaFuncSetAttribute(attn_f16_kernel,
                         cudaFuncAttributeMaxDynamicSharedMemorySize, AT2_SMEM);
    cudaFuncSetAttribute(gemm_fp16_kernel<1, 128>,
                         cudaFuncAttributeMaxDynamicSharedMemorySize, G1_SMEM);
    cudaFuncSetAttribute(gemm_fp16_kernel<0, 64>,
                         cudaFuncAttributeMaxDynamicSharedMemorySize, G2_SMEM);

    const int M = MROWS;  // 8192

    // 0) convert x -> fp16; transpose+convert weights -> [N,K] fp16
    cvt_fp16_kernel<<<(M * EMB / 4 + 255) / 256, 256>>>(x, x16, M * EMB / 4);
    transpose_fp16_kernel<<<dim3(EMB3 / 32, EMB / 32), dim3(32, 8)>>>(
        W_attn, wat16, EMB, EMB3);
    transpose_fp16_kernel<<<dim3(EMB / 32, EMB / 32), dim3(32, 8)>>>(
        W_proj, wpt16, EMB, EMB);

    // 1) QKV GEMM (fp16 mma, BK=96) -> Qs|K fp16 + V^T fp16
    gemm_fp16_kernel<1, 128><<<dim3(EMB3 / 128, M / 128), 256, G1_SMEM>>>(
        x16, wat16, b_attn, nullptr, qk16, vt16, M, EMB3, EMB);

    // 2) causal MHA (fp16 mma, log2-domain softmax, f16x2 exp) -> fp16 [M,768]
    attn_f16_kernel<<<dim3(SEQ / 128, BATCH * NHEAD), 256, AT2_SMEM>>>(
        qk16, vt16, at16);

    // 3) out = att @ W_proj + b_proj  (fp16 mma, BK=96, 64-row tiles)
    gemm_fp16_kernel<0, 64><<<dim3(EMB / 128, M / 64), 256, G2_SMEM>>>(
        at16, wpt16, b_proj, out, nullptr, nullptr, M, EMB, EMB);
}

// round 16
// speedup vs baseline: 1.0636x; 1.0636x over previous
#include <cuda_runtime.h>
#include <cuda_fp16.h>
#include <cstdint>

#define EMB   768
#define EMB3  2304
#define NHEAD 12
#define HDIM  64
#define SEQ   1024
#define BATCH 8
#define MROWS (BATCH * SEQ)   // 8192

// Q pre-scale: 0.125 * log2(e)  (folded into Q at GEMM1 epilogue)
#define QSCALE 0.1803368787f

// ---------------------------------------------------------------------------
// Scratch (no cudaMalloc allowed).
// ---------------------------------------------------------------------------
__device__ __align__(256) __half g_x16 [(size_t)MROWS * EMB];       // x fp16
__device__ __align__(256) __half g_wat16[(size_t)EMB3 * EMB];       // W_attn^T [N,K] fp16
__device__ __align__(256) __half g_wpt16[(size_t)EMB * EMB];        // W_proj^T [N,K] fp16
__device__ __align__(256) __half g_qk16[(size_t)MROWS * 2 * EMB];   // Qs|K fp16 [M,1536]
__device__ __align__(256) __half g_vt16[(size_t)BATCH * NHEAD * HDIM * SEQ]; // V^T fp16 [B,H,d,t]
__device__ __align__(256) __half g_at16[(size_t)MROWS * EMB];       // attn out fp16

// ---------------------------------------------------------------------------
// Helpers
// ---------------------------------------------------------------------------
__device__ __forceinline__ void cpa16(void* smem_dst, const void* gmem_src) {
    uint32_t s = (uint32_t)__cvta_generic_to_shared(smem_dst);
    asm volatile("cp.async.cg.shared.global [%0], [%1], 16;\n" :: "r"(s), "l"(gmem_src));
}
__device__ __forceinline__ void cpa_commit() { asm volatile("cp.async.commit_group;\n"); }
template<int N>
__device__ __forceinline__ void cpa_wait() { asm volatile("cp.async.wait_group %0;\n" :: "n"(N) : "memory"); }

__device__ __forceinline__ void mma_f16(float& d0, float& d1, float& d2, float& d3,
                                        uint32_t a0, uint32_t a1, uint32_t a2, uint32_t a3,
                                        uint32_t b0, uint32_t b1) {
    asm volatile(
        "mma.sync.aligned.m16n8k16.row.col.f32.f16.f16.f32 "
        "{%0,%1,%2,%3}, {%4,%5,%6,%7}, {%8,%9}, {%0,%1,%2,%3};\n"
        : "+f"(d0), "+f"(d1), "+f"(d2), "+f"(d3)
        : "r"(a0), "r"(a1), "r"(a2), "r"(a3), "r"(b0), "r"(b1));
}

__device__ __forceinline__ void ldsm4(uint32_t& r0, uint32_t& r1,
                                      uint32_t& r2, uint32_t& r3, uint32_t addr) {
    asm volatile("ldmatrix.sync.aligned.m8n8.x4.shared.b16 {%0,%1,%2,%3}, [%4];"
                 : "=r"(r0), "=r"(r1), "=r"(r2), "=r"(r3) : "r"(addr));
}

__device__ __forceinline__ uint32_t pack_f16x2(float lo, float hi) {
    uint32_t u;
    asm("cvt.rn.f16x2.f32 %0, %1, %2;" : "=r"(u) : "f"(hi), "f"(lo));
    return u;
}

__device__ __forceinline__ float ex2f(float x) {
    float y;
    asm("ex2.approx.f32 %0, %1;" : "=f"(y) : "f"(x));
    return y;
}

// ---------------------------------------------------------------------------
// Pre-pass 1: fp32 -> fp16 (float4 -> 2x half2)
// ---------------------------------------------------------------------------
__global__ void cvt_fp16_kernel(const float* __restrict__ in, __half* __restrict__ out, int n4)
{
    int i = blockIdx.x * blockDim.x + threadIdx.x;
    if (i < n4) {
        float4 v = ((const float4*)in)[i];
        ((__half2*)out)[2 * i]     = __floats2half2_rn(v.x, v.y);
        ((__half2*)out)[2 * i + 1] = __floats2half2_rn(v.z, v.w);
    }
}

// ---------------------------------------------------------------------------
// Pre-pass 2: W[K,N] fp32 -> W^T[N,K] fp16 (32x32 smem-tiled transpose)
// ---------------------------------------------------------------------------
__global__ void transpose_fp16_kernel(const float* __restrict__ W,
                                      __half* __restrict__ T, int K, int N)
{
    __shared__ float t[32][33];
    const int tx = threadIdx.x, ty = threadIdx.y;
    const int n0 = blockIdx.x * 32, k0 = blockIdx.y * 32;
#pragma unroll
    for (int i = 0; i < 4; i++)
        t[ty + i * 8][tx] = W[(size_t)(k0 + ty + i * 8) * N + n0 + tx];
    __syncthreads();
#pragma unroll
    for (int i = 0; i < 4; i++) {
        const int n = ty + i * 8;
        T[(size_t)(n0 + n) * K + k0 + tx] = __float2half_rn(t[tx][n]);
    }
}

// ---------------------------------------------------------------------------
// FP16 tensor-core GEMM (round-14 proven config): C = A @ B^T + bias.
// MT x 128 tile, BK=64, 256 thr, m16n8k16, ldmatrix, pitch 36 words.
// MODE 0: C fp32 [M,N]; MODE 1 (MT=128): QKV layout, Q pre-scaled by QSCALE.
// ---------------------------------------------------------------------------
#define GW 36   // smem pitch in 32-bit words (32 data + 4 pad)

template<int MODE, int MT>
__global__ __launch_bounds__(256)
void gemm_fp16_kernel(const __half* __restrict__ A, const __half* __restrict__ B,
                      const float* __restrict__ bias, float* __restrict__ C,
                      __half* __restrict__ QK, __half* __restrict__ VT,
                      int M, int N, int K)
{
    constexpr int MI = MT / 32;
    constexpr int AW = MT * GW;
    constexpr int SW = AW + 128 * GW;

    extern __shared__ uint32_t gsm[];

    const int tid    = threadIdx.x;
    const int lane   = tid & 31;
    const int warp   = tid >> 5;
    const int warp_m = warp >> 2;
    const int warp_n = warp & 3;
    const int gr     = lane >> 2;
    const int gc     = lane & 3;

    const int brow = blockIdx.y * MT;
    const int bcol = blockIdx.x * 128;

    const int lrow8 = lane & 7;
    const int segA  = (lane >> 3) & 1;
    const int segAc = lane >> 4;
    const int aLw = (segA * 8 + lrow8) * GW + segAc * 4;
    const int bLw = (segAc * 8 + lrow8) * GW + segA * 4;

    const uint32_t smb = (uint32_t)__cvta_generic_to_shared(gsm);

    float acc[MI][4][4];
#pragma unroll
    for (int i = 0; i < MI; i++)
#pragma unroll
        for (int j = 0; j < 4; j++)
#pragma unroll
            for (int v = 0; v < 4; v++) acc[i][j][v] = 0.f;

    const int NCH = K / 64;

    auto load_stage = [&](int s, int kc) {
        uint32_t* st = gsm + s * SW;
#pragma unroll
        for (int i = tid; i < MT * 8; i += 256) {
            const int r = i >> 3, u = i & 7;
            cpa16(st + r * GW + u * 4, A + (size_t)(brow + r) * K + kc + u * 8);
        }
#pragma unroll
        for (int i = tid; i < 128 * 8; i += 256) {
            const int r = i >> 3, u = i & 7;
            cpa16(st + AW + r * GW + u * 4, B + (size_t)(bcol + r) * K + kc + u * 8);
        }
    };

    load_stage(0, 0);
    cpa_commit();

    int buf = 0;
    for (int c = 0; c < NCH; c++) {
        cpa_wait<0>();
        __syncthreads();

        if (c + 1 < NCH) {
            load_stage(buf ^ 1, (c + 1) * 64);
            cpa_commit();
        }

        const uint32_t aBase = smb + (uint32_t)(buf * SW) * 4;
        const uint32_t bBase = smb + (uint32_t)(buf * SW + AW) * 4;

#pragma unroll
        for (int ks = 0; ks < 4; ks++) {
            const int w0 = ks * 8;
            uint32_t af[MI][4], bf[4][2];
#pragma unroll
            for (int mi = 0; mi < MI; mi++)
                ldsm4(af[mi][0], af[mi][1], af[mi][2], af[mi][3],
                      aBase + (uint32_t)(((warp_m * (MT / 2) + mi * 16) * GW + w0 + aLw) * 4));
#pragma unroll
            for (int p = 0; p < 2; p++)
                ldsm4(bf[2 * p][0], bf[2 * p][1], bf[2 * p + 1][0], bf[2 * p + 1][1],
                      bBase + (uint32_t)(((warp_n * 32 + p * 16) * GW + w0 + bLw) * 4));
#pragma unroll
            for (int mi = 0; mi < MI; mi++)
#pragma unroll
                for (int ni = 0; ni < 4; ni++)
                    mma_f16(acc[mi][ni][0], acc[mi][ni][1],
                            acc[mi][ni][2], acc[mi][ni][3],
                            af[mi][0], af[mi][1], af[mi][2], af[mi][3],
                            bf[ni][0], bf[ni][1]);
        }
        buf ^= 1;
    }

    // Epilogue
#pragma unroll
    for (int ni = 0; ni < 4; ni++) {
        const int col = bcol + warp_n * 32 + ni * 8 + 2 * gc;
        const float bv0 = bias[col];
        const float bv1 = bias[col + 1];
#pragma unroll
        for (int mi = 0; mi < MI; mi++) {
            const int row = brow + warp_m * (MT / 2) + mi * 16 + gr;
            float v00 = acc[mi][ni][0] + bv0, v01 = acc[mi][ni][1] + bv1;
            float v10 = acc[mi][ni][2] + bv0, v11 = acc[mi][ni][3] + bv1;
            if (MODE == 0) {
                *(float2*)&C[(size_t)row * N + col]       = make_float2(v00, v01);
                *(float2*)&C[(size_t)(row + 8) * N + col] = make_float2(v10, v11);
            } else {
                if (col < 1536) {
                    if (col < 768) {
                        v00 *= QSCALE; v01 *= QSCALE; v10 *= QSCALE; v11 *= QSCALE;
                    }
                    *(__half2*)&QK[(size_t)row * 1536 + col] = __floats2half2_rn(v00, v01);
                    *(__half2*)&QK[(size_t)(row + 8) * 1536 + col] = __floats2half2_rn(v10, v11);
                } else {
                    const int cc = col - 1536;
                    const int h  = cc >> 6;
                    const int d0 = cc & 63;
                    const int b  = row >> 10;
                    const int t  = row & 1023;
                    __half* base = VT + ((size_t)(b * NHEAD + h) * HDIM) * SEQ;
                    base[(size_t)d0 * SEQ + t]           = __float2half_rn(v00);
                    base[(size_t)(d0 + 1) * SEQ + t]     = __float2half_rn(v01);
                    base[(size_t)d0 * SEQ + t + 8]       = __float2half_rn(v10);
                    base[(size_t)(d0 + 1) * SEQ + t + 8] = __float2half_rn(v11);
                }
            }
        }
    }
}

#define G1_SMEM (2 * (128 + 128) * GW * 4)   // 73728 B
#define G2_SMEM (2 * (64 + 128) * GW * 4)    // 55296 B

// ---------------------------------------------------------------------------
// FP16 tensor-core flash attention (causal, m16n8k16, log2-domain fp32
// softmax).  128-key cp.async stages (one barrier per 128 keys), processed
// as two 64-key sub-passes; per-sub-pass warp-strip causal skip.
// Sub-tile layout: 4 x (64 x APW) buffers for K and for Vt
// (stage s occupies sub-tiles 2s, 2s+1; double-buffered over s&1).
// ---------------------------------------------------------------------------
#define APW 36
#define AT3_SMEM ((128 * APW + 4 * 64 * APW + 4 * 64 * APW) * 4)   // 92160 B

__global__ __launch_bounds__(256, 2)
void attn_f16_kernel(const __half* __restrict__ qk, const __half* __restrict__ vt,
                     __half* __restrict__ out16)
{
    extern __shared__ uint32_t smw[];
    uint32_t* QP  = smw;                   // 128 x APW : Q tile, later P strips
    uint32_t* Ks0 = QP + 128 * APW;        // 4 x 64 x APW (key sub-tiles)
    uint32_t* Vt0 = Ks0 + 4 * 64 * APW;    // 4 x 64 x APW (V^T sub-tiles)

    const int tid  = threadIdx.x;
    const int lane = tid & 31;
    const int warp = tid >> 5;
    const int gr   = lane >> 2;
    const int gc   = lane & 3;

    const int bh = blockIdx.y;
    const int b  = bh / NHEAD;
    const int h  = bh % NHEAD;
    const int qt = 7 - blockIdx.x;
    const int qbase = qt * 128;
    const int nst = qt + 1;                // 128-key stages

    const int lrow8 = lane & 7;
    const int segA  = (lane >> 3) & 1;
    const int segAc = lane >> 4;
    const int aLw = (segA * 8 + lrow8) * APW + segAc * 4;
    const int bLw = (segAc * 8 + lrow8) * APW + segA * 4;

    const uint32_t qpb = (uint32_t)__cvta_generic_to_shared(QP);
    const uint32_t ksb = (uint32_t)__cvta_generic_to_shared(Ks0);
    const uint32_t vtb = (uint32_t)__cvta_generic_to_shared(Vt0);

    const __half* kcol = qk + (size_t)b * SEQ * 1536 + 768 + h * HDIM;
    const __half* vrow = vt + (size_t)(b * NHEAD + h) * HDIM * SEQ;

    // Stage loader: keys [kc, kc+128) -> K sub-tiles (s2, s2+1), Vt likewise.
    // K: 128 key-rows x 8 16B-units.  Vt: 64 d-rows x 16 units (2 sub-tiles).
    auto load_stage = [&](int s2, int kc) {
#pragma unroll
        for (int i = tid; i < 128 * 8; i += 256) {
            const int r = i >> 3, u = i & 7;
            cpa16(Ks0 + (s2 + (r >> 6)) * 64 * APW + (r & 63) * APW + u * 4,
                  kcol + (size_t)(kc + r) * 1536 + u * 8);
        }
#pragma unroll
        for (int i = tid; i < 64 * 16; i += 256) {
            const int d = i >> 4, u = i & 15;
            cpa16(Vt0 + (s2 + (u >> 3)) * 64 * APW + d * APW + (u & 7) * 4,
                  vrow + (size_t)d * SEQ + kc + (u >> 3) * 64 + (u & 7) * 8);
        }
    };

    // Q tile load
    {
        const int r = tid >> 1;
        const int u = (tid & 1) * 4;
        const __half* src = qk + (size_t)(b * SEQ + qbase + r) * 1536 + h * HDIM + u * 8;
        uint32_t* dst = QP + r * APW + u * 4;
#pragma unroll
        for (int i = 0; i < 4; i++)
            cpa16(dst + 4 * i, src + 8 * i);
    }
    load_stage(0, 0);
    cpa_commit();
    cpa_wait<0>();
    __syncthreads();

    uint32_t qf[4][4];
#pragma unroll
    for (int c = 0; c < 4; c++)
        ldsm4(qf[c][0], qf[c][1], qf[c][2], qf[c][3],
              qpb + (uint32_t)(((warp * 16) * APW + c * 8 + aLw) * 4));

    float o[8][4];
#pragma unroll
    for (int i = 0; i < 8; i++)
#pragma unroll
        for (int j = 0; j < 4; j++) o[i][j] = 0.f;
    float mr0 = -1e30f, mr1 = -1e30f, l0 = 0.f, l1 = 0.f;

    const int lrow = warp * 16 + gr;
    const int grow0 = qbase + lrow;
    const int prow0 = lrow * APW;
    const int prow1 = (lrow + 8) * APW;

    int buf = 0;
    for (int st = 0; st < nst; st++) {
        cpa_wait<0>();
        __syncthreads();

        if (st + 1 < nst) {
            load_stage((buf ^ 1) * 2, (st + 1) * 128);
            cpa_commit();
        }

#pragma unroll
        for (int half = 0; half < 2; half++) {
            const int kbase = st * 128 + half * 64;
            if (kbase > qbase + warp * 16 + 15) continue;   // strip fully masked

            const int sub = buf * 2 + half;

            // ---- S' = Qs @ K^T (log2 domain) ----
            float s[8][4];
#pragma unroll
            for (int i = 0; i < 8; i++)
#pragma unroll
                for (int j = 0; j < 4; j++) s[i][j] = 0.f;

            const uint32_t kBase = ksb + (uint32_t)sub * (64 * APW * 4);
#pragma unroll
            for (int c = 0; c < 4; c++) {
                const int w0 = c * 8;
                uint32_t bf[8][2];
#pragma unroll
                for (int p = 0; p < 4; p++)
                    ldsm4(bf[2 * p][0], bf[2 * p][1], bf[2 * p + 1][0], bf[2 * p + 1][1],
                          kBase + (uint32_t)(((p * 16) * APW + w0 + bLw) * 4));
#pragma unroll
                for (int nt = 0; nt < 8; nt++)
                    mma_f16(s[nt][0], s[nt][1], s[nt][2], s[nt][3],
                            qf[c][0], qf[c][1], qf[c][2], qf[c][3],
                            bf[nt][0], bf[nt][1]);
            }

            // ---- causal mask ----
            if (kbase + 63 > grow0) {
                const int lr0 = grow0;
                const int lr1 = grow0 + 8;
#pragma unroll
                for (int nt = 0; nt < 8; nt++) {
                    const int c0 = kbase + nt * 8 + 2 * gc;
                    if (c0     > lr0) s[nt][0] = -1e30f;
                    if (c0 + 1 > lr0) s[nt][1] = -1e30f;
                    if (c0     > lr1) s[nt][2] = -1e30f;
                    if (c0 + 1 > lr1) s[nt][3] = -1e30f;
                }
            }

            // ---- online softmax (log2 domain, fp32) ----
            float mx0 = -1e30f, mx1 = -1e30f;
#pragma unroll
            for (int nt = 0; nt < 8; nt++) {
                mx0 = fmaxf(mx0, fmaxf(s[nt][0], s[nt][1]));
                mx1 = fmaxf(mx1, fmaxf(s[nt][2], s[nt][3]));
            }
            mx0 = fmaxf(mx0, __shfl_xor_sync(0xffffffffu, mx0, 1));
            mx0 = fmaxf(mx0, __shfl_xor_sync(0xffffffffu, mx0, 2));
            mx1 = fmaxf(mx1, __shfl_xor_sync(0xffffffffu, mx1, 1));
            mx1 = fmaxf(mx1, __shfl_xor_sync(0xffffffffu, mx1, 2));

            const float mn0 = fmaxf(mr0, mx0);
            const float mn1 = fmaxf(mr1, mx1);
            const float a0  = ex2f(mr0 - mn0);
            const float a1  = ex2f(mr1 - mn1);
            mr0 = mn0; mr1 = mn1;

            float sum0 = 0.f, sum1 = 0.f;
#pragma unroll
            for (int nt = 0; nt < 8; nt++) {
                s[nt][0] = ex2f(s[nt][0] - mn0);
                s[nt][1] = ex2f(s[nt][1] - mn0);
                s[nt][2] = ex2f(s[nt][2] - mn1);
                s[nt][3] = ex2f(s[nt][3] - mn1);
                sum0 += s[nt][0] + s[nt][1];
                sum1 += s[nt][2] + s[nt][3];
            }
            sum0 += __shfl_xor_sync(0xffffffffu, sum0, 1);
            sum0 += __shfl_xor_sync(0xffffffffu, sum0, 2);
            sum1 += __shfl_xor_sync(0xffffffffu, sum1, 1);
            sum1 += __shfl_xor_sync(0xffffffffu, sum1, 2);
            l0 = l0 * a0 + sum0;
            l1 = l1 * a1 + sum1;

#pragma unroll
            for (int nt = 0; nt < 8; nt++) {
                o[nt][0] *= a0; o[nt][1] *= a0;
                o[nt][2] *= a1; o[nt][3] *= a1;
            }

            // ---- P (fp16) -> warp-local smem strip ----
#pragma unroll
            for (int nt = 0; nt < 8; nt++) {
                QP[prow0 + nt * 4 + gc] = pack_f16x2(s[nt][0], s[nt][1]);
                QP[prow1 + nt * 4 + gc] = pack_f16x2(s[nt][2], s[nt][3]);
            }
            __syncwarp();

            // ---- O += P @ V ----
            const uint32_t vBase = vtb + (uint32_t)sub * (64 * APW * 4);
#pragma unroll
            for (int c = 0; c < 4; c++) {
                const int w0 = c * 8;
                uint32_t af[4];
                ldsm4(af[0], af[1], af[2], af[3],
                      qpb + (uint32_t)(((warp * 16) * APW + w0 + aLw) * 4));
                uint32_t bf[8][2];
#pragma unroll
                for (int p = 0; p < 4; p++)
                    ldsm4(bf[2 * p][0], bf[2 * p][1], bf[2 * p + 1][0], bf[2 * p + 1][1],
                          vBase + (uint32_t)(((p * 16) * APW + w0 + bLw) * 4));
#pragma unroll
                for (int nt = 0; nt < 8; nt++)
                    mma_f16(o[nt][0], o[nt][1], o[nt][2], o[nt][3],
                            af[0], af[1], af[2], af[3],
                            bf[nt][0], bf[nt][1]);
            }
            __syncwarp();
        }
        buf ^= 1;
    }

    // ---- epilogue ----
    const float inv0 = 1.f / l0;
    const float inv1 = 1.f / l1;
    const int r0g = b * SEQ + grow0;
#pragma unroll
    for (int nt = 0; nt < 8; nt++) {
        const int col = h * HDIM + nt * 8 + 2 * gc;
        *(__half2*)&out16[(size_t)r0g * EMB + col] =
            __floats2half2_rn(o[nt][0] * inv0, o[nt][1] * inv0);
        *(__half2*)&out16[(size_t)(r0g + 8) * EMB + col] =
            __floats2half2_rn(o[nt][2] * inv1, o[nt][3] * inv1);
    }
}

// ---------------------------------------------------------------------------
extern "C" void kernel_launch(void* const* d_in, const int* in_sizes, int n_in,
                              void* d_out, int out_size)
{
    const float* x      = (const float*)d_in[0];
    const float* W_attn = (const float*)d_in[1];
    const float* b_attn = (const float*)d_in[2];
    const float* W_proj = (const float*)d_in[3];
    const float* b_proj = (const float*)d_in[4];
    float* out = (float*)d_out;

    __half *x16, *wat16, *wpt16, *qk16, *vt16, *at16;
    cudaGetSymbolAddress((void**)&x16,   g_x16);
    cudaGetSymbolAddress((void**)&wat16, g_wat16);
    cudaGetSymbolAddress((void**)&wpt16, g_wpt16);
    cudaGetSymbolAddress((void**)&qk16,  g_qk16);
    cudaGetSymbolAddress((void**)&vt16,  g_vt16);
    cudaGetSymbolAddress((void**)&at16,  g_at16);

    cudaFuncSetAttribute(attn_f16_kernel,
                         cudaFuncAttributeMaxDynamicSharedMemorySize, AT3_SMEM);
    cudaFuncSetAttribute(gemm_fp16_kernel<1, 128>,
                         cudaFuncAttributeMaxDynamicSharedMemorySize, G1_SMEM);
    cudaFuncSetAttribute(gemm_fp16_kernel<0, 64>,
                         cudaFuncAttributeMaxDynamicSharedMemorySize, G2_SMEM);

    const int M = MROWS;  // 8192

    // 0) convert x -> fp16; transpose+convert weights -> [N,K] fp16
    cvt_fp16_kernel<<<(M * EMB / 4 + 255) / 256, 256>>>(x, x16, M * EMB / 4);
    transpose_fp16_kernel<<<dim3(EMB3 / 32, EMB / 32), dim3(32, 8)>>>(
        W_attn, wat16, EMB, EMB3);
    transpose_fp16_kernel<<<dim3(EMB / 32, EMB / 32), dim3(32, 8)>>>(
        W_proj, wpt16, EMB, EMB);

    // 1) QKV GEMM (fp16 mma, BK=64) -> Qs|K fp16 + V^T fp16
    gemm_fp16_kernel<1, 128><<<dim3(EMB3 / 128, M / 128), 256, G1_SMEM>>>(
        x16, wat16, b_attn, nullptr, qk16, vt16, M, EMB3, EMB);

    // 2) causal MHA (fp16 mma, 128-key stages) -> fp16 [M,768]
    attn_f16_kernel<<<dim3(SEQ / 128, BATCH * NHEAD), 256, AT3_SMEM>>>(
        qk16, vt16, at16);

    // 3) out = att @ W_proj + b_proj  (fp16 mma, BK=64, 64-row tiles)
    gemm_fp16_kernel<0, 64><<<dim3(EMB / 128, M / 64), 256, G2_SMEM>>>(
        at16, wpt16, b_proj, out, nullptr, nullptr, M, EMB, EMB);
}